// round 8
// baseline (speedup 1.0000x reference)
#include <cuda_runtime.h>
#include <cuda_fp16.h>
#include <cstdint>

// ---------------- problem constants ----------------
#define NSZ      1024
#define M_TOTAL  32768

// GEMM tiling: CTA 128x128, 4 warps of 64x64
#define BM 128
#define BN 128
#define BK 64                       // halves per K chunk (128 bytes per smem row)
#define STG 3
#define NKC (NSZ / BK)              // 16 K-chunks
#define ROWB 128                    // bytes per smem row
#define A_BYTES (BM * ROWB)         // 16384
#define B_BYTES (BN * ROWB)         // 16384
#define STAGE_B (A_BYTES + B_BYTES) // 32768
#define SMEM_TOTAL (STG * STAGE_B)  // 98304
#define GTHR 128

// fused pre-pass: 64 sinkhorn CTAs + 84 xconv CTAs, all co-resident
#define SK_CTA  64
#define TOT_CTA 148
#define XC_CTA  (TOT_CTA - SK_CTA)  // 84
#define THR     512
#define RPC     (NSZ / SK_CTA)      // 16 rows (and cols) per sinkhorn CTA
#define N_ITER  10
#define TOTAL4  (M_TOTAL * NSZ / 4) // 8388608 float4s of x
#define XSPLIT  ((int)(((long long)TOTAL4 * 39) / 50))   // 78% to dedicated CTAs

// ---------------- scratch (no allocation allowed) ----------------
__device__ __align__(1024) __half g_xh[(size_t)M_TOTAL * NSZ];   // 64 MiB fp16 x
__device__ __align__(1024) __half g_wh[NSZ * NSZ];               // 2 MiB fp16 W
__device__ __align__(1024) float  g_E  [NSZ * NSZ];              // 4 MiB exp(W/T) fp32 (final W)
__device__ __align__(1024) __half g_Eh [NSZ * NSZ];              // 2 MiB fp16 E   (sweeps)
__device__ __align__(1024) __half g_ETh[NSZ * NSZ];              // 2 MiB fp16 E^T (sweeps)
__device__ float g_u[NSZ];
__device__ float g_v[NSZ];
__device__ int g_bar_cnt;
__device__ int g_bar_gen;

// ---------------- helpers ----------------
__device__ __forceinline__ uint32_t smem_u32(const void* p) {
    uint32_t a;
    asm("{ .reg .u64 t; cvta.to.shared.u64 t, %1; cvt.u32.u64 %0, t; }" : "=r"(a) : "l"(p));
    return a;
}
__device__ __forceinline__ uint32_t swz(uint32_t o) {       // 128B swizzle
    return o ^ ((o >> 3) & 0x70);
}
__device__ __forceinline__ void cp_async16(uint32_t saddr, const void* gaddr) {
    asm volatile("cp.async.cg.shared.global [%0], [%1], 16;" :: "r"(saddr), "l"(gaddr));
}
__device__ __forceinline__ void ldsm_x4(uint32_t* r, uint32_t addr) {
    asm volatile("ldmatrix.sync.aligned.m8n8.x4.shared.b16 {%0,%1,%2,%3}, [%4];"
                 : "=r"(r[0]), "=r"(r[1]), "=r"(r[2]), "=r"(r[3]) : "r"(addr));
}
__device__ __forceinline__ void mma16816(float* d, const uint32_t* a, const uint32_t* b) {
    asm volatile(
        "mma.sync.aligned.m16n8k16.row.col.f32.f16.f16.f32 "
        "{%0,%1,%2,%3}, {%4,%5,%6,%7}, {%8,%9}, {%0,%1,%2,%3};"
        : "+f"(d[0]), "+f"(d[1]), "+f"(d[2]), "+f"(d[3])
        : "r"(a[0]), "r"(a[1]), "r"(a[2]), "r"(a[3]), "r"(b[0]), "r"(b[1]));
}
__device__ __forceinline__ uint2 pack_half4(float4 f) {
    __half2 h0 = __floats2half2_rn(f.x, f.y);
    __half2 h1 = __floats2half2_rn(f.z, f.w);
    uint2 u;
    u.x = *reinterpret_cast<uint32_t*>(&h0);
    u.y = *reinterpret_cast<uint32_t*>(&h1);
    return u;
}

// light grid barrier over the SK_CTA sinkhorn CTAs: release/acquire chain on
// (cnt, gen); NO threadfence / CCTL. Cross-CTA data uses __ldcg/__stcg.
__device__ __forceinline__ void sk_barrier() {
    __syncthreads();
    if (threadIdx.x == 0) {
        int gen;
        asm volatile("ld.acquire.gpu.global.s32 %0, [%1];"
                     : "=r"(gen) : "l"(&g_bar_gen) : "memory");
        int prev;
        asm volatile("atom.release.gpu.global.add.s32 %0, [%1], %2;"
                     : "=r"(prev) : "l"(&g_bar_cnt), "r"(1) : "memory");
        if (prev == SK_CTA - 1) {
            asm volatile("st.relaxed.gpu.global.s32 [%0], %1;"
                         :: "l"(&g_bar_cnt), "r"(0) : "memory");
            asm volatile("st.release.gpu.global.s32 [%0], %1;"
                         :: "l"(&g_bar_gen), "r"(gen + 1) : "memory");
        } else {
            int cur;
            do {
                __nanosleep(32);
                asm volatile("ld.acquire.gpu.global.s32 %0, [%1];"
                             : "=r"(cur) : "l"(&g_bar_gen) : "memory");
            } while (cur == gen);
        }
    }
    __syncthreads();
}

// exp with cheap polynomial for tiny args (off-diagonal entries ~1e-4)
__device__ __forceinline__ float exp_mixed(float x) {
    if (fabsf(x) < 0.125f) {
        float p = fmaf(x, 1.0f / 24.0f, 1.0f / 6.0f);
        p = fmaf(p, x, 0.5f);
        p = fmaf(p, x, 1.0f);
        p = fmaf(p, x, 1.0f);
        return p;
    }
    return __expf(x);
}

__device__ __forceinline__ void xconv_range(const float4* __restrict__ x,
                                            uint2* __restrict__ xh,
                                            int start, int end, int stride) {
    #pragma unroll 4
    for (int i = start; i < end; i += stride) {
        float4 f = __ldcs(&x[i]);
        xh[i] = pack_half4(f);
    }
}

// ---------------- kernel 1: fused pre-pass -----------------------------
// CTAs [0, SK_CTA): linear-domain sinkhorn on E = exp(W/T):
//     u' = sqrt(u / (E v)),  v' = sqrt(v / (E^T u)),  10 iters (fp16 sweeps),
//     then wh = E * u ⊗ v (fp16, from fp32 E), then 22% xconv tail.
// CTAs [SK_CTA, TOT_CTA): convert first 78% of x fp32 -> fp16.
__global__ void __launch_bounds__(THR, 1) fused_pre_kernel(
    const float4* __restrict__ x, const float* __restrict__ w,
    __half* __restrict__ wh, uint2* __restrict__ xh)
{
    const int tid = threadIdx.x;

    if (blockIdx.x >= SK_CTA) {
        xconv_range(x, xh, (blockIdx.x - SK_CTA) * THR + tid, XSPLIT, XC_CTA * THR);
        return;
    }

    // ---------------- sinkhorn part ----------------
    __shared__ __align__(16) float sE[8 * 1032];   // transpose staging (33 KB)
    __shared__ __align__(16) float su[NSZ];
    __shared__ __align__(16) float sv[NSZ];

    const int b   = blockIdx.x;
    const int wid = tid >> 5, lid = tid & 31;
    const int rb  = b * RPC;                      // own rows / own cols

    // ---- phase 0: E = exp(w*8) (fp32 + fp16), ETh = E^T (fp16), u = v = 1 ----
    #pragma unroll 1
    for (int g = 0; g < RPC / 8; g++) {
        const int r0 = rb + 8 * g;
        const float4* wp = reinterpret_cast<const float4*>(w + (size_t)r0 * NSZ);
        float4* ep  = reinterpret_cast<float4*>(g_E  + (size_t)r0 * NSZ);
        uint2*  ehp = reinterpret_cast<uint2*> (g_Eh + (size_t)r0 * NSZ);
        for (int i = tid; i < 8 * NSZ / 4; i += THR) {
            float4 f = wp[i];
            float4 e;
            e.x = exp_mixed(f.x * 8.0f);
            e.y = exp_mixed(f.y * 8.0f);
            e.z = exp_mixed(f.z * 8.0f);
            e.w = exp_mixed(f.w * 8.0f);
            ep[i]  = e;
            ehp[i] = pack_half4(e);
            int row = i >> 8, c4 = i & 255;
            reinterpret_cast<float4*>(sE + row * 1032)[c4] = e;
        }
        __syncthreads();
        for (int j = tid; j < NSZ; j += THR) {
            __half2 p0 = __floats2half2_rn(sE[0 * 1032 + j], sE[1 * 1032 + j]);
            __half2 p1 = __floats2half2_rn(sE[2 * 1032 + j], sE[3 * 1032 + j]);
            __half2 p2 = __floats2half2_rn(sE[4 * 1032 + j], sE[5 * 1032 + j]);
            __half2 p3 = __floats2half2_rn(sE[6 * 1032 + j], sE[7 * 1032 + j]);
            uint4 o;
            o.x = *reinterpret_cast<uint32_t*>(&p0);
            o.y = *reinterpret_cast<uint32_t*>(&p1);
            o.z = *reinterpret_cast<uint32_t*>(&p2);
            o.w = *reinterpret_cast<uint32_t*>(&p3);
            *reinterpret_cast<uint4*>(g_ETh + (size_t)j * NSZ + r0) = o;
        }
        __syncthreads();
    }
    if (tid < RPC) {
        __stcg(&g_u[rb + tid], 1.0f);
        __stcg(&g_v[rb + tid], 1.0f);
    }
    sk_barrier();

    // ---- iterations: one light barrier each; 1 row + 1 col per warp ----
    for (int it = 0; it < N_ITER; it++) {
        if (tid < NSZ / 4) {
            reinterpret_cast<float4*>(su)[tid] = __ldcg(reinterpret_cast<const float4*>(g_u) + tid);
            reinterpret_cast<float4*>(sv)[tid] = __ldcg(reinterpret_cast<const float4*>(g_v) + tid);
        }
        __syncthreads();

        const int idx = rb + wid;   // own row (in E) == own col (row in ETh)
        const uint4* er = reinterpret_cast<const uint4*>(g_Eh  + (size_t)idx * NSZ);
        const uint4* tr = reinterpret_cast<const uint4*>(g_ETh + (size_t)idx * NSZ);
        float s_u = 0.f, s_v = 0.f;
        #pragma unroll
        for (int k = 0; k < 4; k++) {
            int q = lid + 32 * k;                 // uint4 index (8 halfs)
            uint4 e = er[q], t = tr[q];
            const float4* vp = reinterpret_cast<const float4*>(sv) + 2 * q;
            const float4* up = reinterpret_cast<const float4*>(su) + 2 * q;
            float4 v0 = vp[0], v1 = vp[1];
            float4 u0 = up[0], u1 = up[1];
            float2 f;
            f = __half22float2(*reinterpret_cast<__half2*>(&e.x));
            s_u = fmaf(f.x, v0.x, s_u); s_u = fmaf(f.y, v0.y, s_u);
            f = __half22float2(*reinterpret_cast<__half2*>(&e.y));
            s_u = fmaf(f.x, v0.z, s_u); s_u = fmaf(f.y, v0.w, s_u);
            f = __half22float2(*reinterpret_cast<__half2*>(&e.z));
            s_u = fmaf(f.x, v1.x, s_u); s_u = fmaf(f.y, v1.y, s_u);
            f = __half22float2(*reinterpret_cast<__half2*>(&e.w));
            s_u = fmaf(f.x, v1.z, s_u); s_u = fmaf(f.y, v1.w, s_u);
            f = __half22float2(*reinterpret_cast<__half2*>(&t.x));
            s_v = fmaf(f.x, u0.x, s_v); s_v = fmaf(f.y, u0.y, s_v);
            f = __half22float2(*reinterpret_cast<__half2*>(&t.y));
            s_v = fmaf(f.x, u0.z, s_v); s_v = fmaf(f.y, u0.w, s_v);
            f = __half22float2(*reinterpret_cast<__half2*>(&t.z));
            s_v = fmaf(f.x, u1.x, s_v); s_v = fmaf(f.y, u1.y, s_v);
            f = __half22float2(*reinterpret_cast<__half2*>(&t.w));
            s_v = fmaf(f.x, u1.z, s_v); s_v = fmaf(f.y, u1.w, s_v);
        }
        #pragma unroll
        for (int off = 16; off > 0; off >>= 1) {
            s_u += __shfl_xor_sync(0xffffffffu, s_u, off);
            s_v += __shfl_xor_sync(0xffffffffu, s_v, off);
        }
        if (lid == 0) {
            __stcg(&g_u[idx], sqrtf(su[idx] / s_u));
            __stcg(&g_v[idx], sqrtf(sv[idx] / s_v));
        }
        sk_barrier();
    }

    // ---- final: wh[i][j] = E[i][j] * u_i * v_j (fp16, fp32 E), 1 row/warp ----
    if (tid < NSZ / 4)
        reinterpret_cast<float4*>(sv)[tid] = __ldcg(reinterpret_cast<const float4*>(g_v) + tid);
    __syncthreads();
    {
        int row = rb + wid;
        float ui = __ldcg(&g_u[row]);
        const float4* er = reinterpret_cast<const float4*>(g_E + (size_t)row * NSZ);
        const float4* vr = reinterpret_cast<const float4*>(sv);
        uint2* wr = reinterpret_cast<uint2*>(wh + (size_t)row * NSZ);
        #pragma unroll
        for (int k = 0; k < 8; k++) {
            int idx = lid + 32 * k;
            float4 e = er[idx];
            float4 v4 = vr[idx];
            float4 p = make_float4(e.x * ui * v4.x, e.y * ui * v4.y,
                                   e.z * ui * v4.z, e.w * ui * v4.w);
            wr[idx] = pack_half4(p);
        }
    }

    // ---- tail 22% of xconv ----
    xconv_range(x, xh, XSPLIT + b * THR + tid, TOTAL4, SK_CTA * THR);
}

// ---------------- kernel 2: HMMA fp16 GEMM  y = x @ W^T ----------------
// A = g_xh [M, K] K-contig, B = g_wh [N, K] K-contig, out fp32 [M, N].
// 128 threads, 4 warps (2x2), warp tile 64x64.
__device__ __forceinline__ void load_stage(uint32_t sbase, const __half* __restrict__ A,
                                           const __half* __restrict__ B,
                                           int m_base, int n_base, int kc, int tid) {
    const uint32_t sA = sbase, sB = sbase + A_BYTES;
    const __half* ga = A + (size_t)m_base * NSZ + kc * BK;
    const __half* gb = B + (size_t)n_base * NSZ + kc * BK;
    #pragma unroll
    for (int i = 0; i < 8; i++) {
        int id = tid + i * GTHR;
        int row = id >> 3, c = id & 7;
        cp_async16(sA + swz(row * ROWB + c * 16), ga + row * NSZ + c * 8);
    }
    #pragma unroll
    for (int i = 0; i < 8; i++) {
        int id = tid + i * GTHR;
        int row = id >> 3, c = id & 7;
        cp_async16(sB + swz(row * ROWB + c * 16), gb + row * NSZ + c * 8);
    }
}

__global__ void __launch_bounds__(GTHR, 2) gemm_kernel(
    const __half* __restrict__ A, const __half* __restrict__ B,
    float* __restrict__ out)
{
    extern __shared__ __align__(1024) char smem[];
    const uint32_t sb = smem_u32(smem);
    const int tid = threadIdx.x;
    const int lane = tid & 31;
    const int w = tid >> 5;
    const int wm = w >> 1;          // 0..1 -> M offset wm*64
    const int wn = w & 1;           // 0..1 -> N offset wn*64
    const int n_base = blockIdx.x * BN;
    const int m_base = blockIdx.y * BM;

    float acc[4][8][4];
    #pragma unroll
    for (int i = 0; i < 4; i++)
        #pragma unroll
        for (int j = 0; j < 8; j++)
            #pragma unroll
            for (int q = 0; q < 4; q++) acc[i][j][q] = 0.f;

    const uint32_t aRow = (uint32_t)(wm * 64 + (lane & 15)) * ROWB + ((lane >> 4) * 16);
    const uint32_t bRow = (uint32_t)(wn * 64 + ((lane >> 4) * 8) + (lane & 7)) * ROWB
                        + (((lane >> 3) & 1) * 16);

    load_stage(sb + 0 * STAGE_B, A, B, m_base, n_base, 0, tid);
    asm volatile("cp.async.commit_group;" ::: "memory");
    load_stage(sb + 1 * STAGE_B, A, B, m_base, n_base, 1, tid);
    asm volatile("cp.async.commit_group;" ::: "memory");

    int buf = 0;
    #pragma unroll 1
    for (int kc = 0; kc < NKC; kc++) {
        asm volatile("cp.async.wait_group 1;" ::: "memory");
        __syncthreads();

        if (kc + 2 < NKC) {
            int nb = buf + 2; if (nb >= STG) nb -= STG;
            load_stage(sb + nb * STAGE_B, A, B, m_base, n_base, kc + 2, tid);
        }
        asm volatile("cp.async.commit_group;" ::: "memory");

        const uint32_t sA = sb + buf * STAGE_B;
        const uint32_t sB = sA + A_BYTES;
        #pragma unroll
        for (int ks = 0; ks < 4; ks++) {
            uint32_t af[4][4], bf[4][4];
            #pragma unroll
            for (int mt = 0; mt < 4; mt++)
                ldsm_x4(af[mt], sA + swz(aRow + (uint32_t)mt * 16 * ROWB + ks * 32));
            #pragma unroll
            for (int p = 0; p < 4; p++)
                ldsm_x4(bf[p], sB + swz(bRow + (uint32_t)p * 16 * ROWB + ks * 32));
            #pragma unroll
            for (int mt = 0; mt < 4; mt++)
                #pragma unroll
                for (int nt = 0; nt < 8; nt++)
                    mma16816(acc[mt][nt], af[mt], &bf[nt >> 1][(nt & 1) * 2]);
        }
        buf++; if (buf >= STG) buf = 0;
    }

    const int r0 = m_base + wm * 64 + (lane >> 2);
    const int c0 = n_base + wn * 64 + (lane & 3) * 2;
    #pragma unroll
    for (int mt = 0; mt < 4; mt++) {
        #pragma unroll
        for (int nt = 0; nt < 8; nt++) {
            float* p0 = out + (size_t)(r0 + mt * 16) * NSZ + c0 + nt * 8;
            float* p1 = out + (size_t)(r0 + mt * 16 + 8) * NSZ + c0 + nt * 8;
            *reinterpret_cast<float2*>(p0) = make_float2(acc[mt][nt][0], acc[mt][nt][1]);
            *reinterpret_cast<float2*>(p1) = make_float2(acc[mt][nt][2], acc[mt][nt][3]);
        }
    }
}

// ---------------- host ----------------
extern "C" void kernel_launch(void* const* d_in, const int* in_sizes, int n_in,
                              void* d_out, int out_size) {
    const float* x = (const float*)d_in[0];
    const float* w = (const float*)d_in[1];
    if (in_sizes[0] == NSZ * NSZ && in_sizes[1] != NSZ * NSZ) {  // defensive ordering
        x = (const float*)d_in[1];
        w = (const float*)d_in[0];
    }
    float* out = (float*)d_out;

    void* xh_ptr = nullptr;
    void* wh_ptr = nullptr;
    cudaGetSymbolAddress(&xh_ptr, g_xh);
    cudaGetSymbolAddress(&wh_ptr, g_wh);

    cudaFuncSetAttribute(gemm_kernel, cudaFuncAttributeMaxDynamicSharedMemorySize, SMEM_TOTAL);

    // 1) fused: sinkhorn (CTAs 0..63) + x fp32->fp16 (CTAs 64..147 + tail)
    fused_pre_kernel<<<TOT_CTA, THR>>>((const float4*)x, w,
                                       (__half*)wh_ptr, (uint2*)xh_ptr);

    // 2) GEMM
    gemm_kernel<<<dim3(NSZ / BN, M_TOTAL / BM, 1), GTHR, SMEM_TOTAL>>>(
        (const __half*)xh_ptr, (const __half*)wh_ptr, out);
}

// round 10
// speedup vs baseline: 1.0529x; 1.0529x over previous
#include <cuda_runtime.h>
#include <cuda_fp16.h>
#include <cstdint>

// ---------------- problem constants ----------------
#define NSZ      1024
#define M_TOTAL  32768

// GEMM tiling: CTA 128x128, 4 warps of 64x64
#define BM 128
#define BN 128
#define BK 64                       // halves per K chunk (128 bytes per smem row)
#define STG 3
#define NKC (NSZ / BK)              // 16 K-chunks
#define ROWB 128                    // bytes per smem row
#define A_BYTES (BM * ROWB)         // 16384
#define B_BYTES (BN * ROWB)         // 16384
#define STAGE_B (A_BYTES + B_BYTES) // 32768
#define SMEM_TOTAL (STG * STAGE_B)  // 98304
#define GTHR 128

// fused pre-pass: 64 sinkhorn CTAs + 84 xconv CTAs, all co-resident
#define SK_CTA  64
#define TOT_CTA 148
#define XC_CTA  (TOT_CTA - SK_CTA)  // 84
#define THR     512
#define RPC     (NSZ / SK_CTA)      // 16 rows (and cols) per sinkhorn CTA
#define N_ITER  10
#define TOTAL4  (M_TOTAL * NSZ / 4) // 8388608 float4s of x
#define XSPLIT  (TOTAL4 / 4 * 3)    // 75% to dedicated CTAs (6291456)
#define SKQ     ((TOTAL4 - XSPLIT) / SK_CTA)   // 32768 float4s per sinkhorn CTA

// ---------------- scratch (no allocation allowed) ----------------
__device__ __align__(1024) __half g_xh[(size_t)M_TOTAL * NSZ];   // 64 MiB fp16 x
__device__ __align__(1024) __half g_wh[NSZ * NSZ];               // 2 MiB fp16 W
__device__ __align__(1024) float  g_E [NSZ * NSZ];               // 4 MiB exp(W/T)
__device__ __align__(1024) float  g_ET[NSZ * NSZ];               // 4 MiB transpose
__device__ float g_u[NSZ];
__device__ float g_v[NSZ];
__device__ int          g_bar_cnt;
__device__ volatile int g_bar_gen;

// ---------------- helpers ----------------
__device__ __forceinline__ uint32_t smem_u32(const void* p) {
    uint32_t a;
    asm("{ .reg .u64 t; cvta.to.shared.u64 t, %1; cvt.u32.u64 %0, t; }" : "=r"(a) : "l"(p));
    return a;
}
__device__ __forceinline__ uint32_t swz(uint32_t o) {       // 128B swizzle
    return o ^ ((o >> 3) & 0x70);
}
__device__ __forceinline__ void cp_async16(uint32_t saddr, const void* gaddr) {
    asm volatile("cp.async.cg.shared.global [%0], [%1], 16;" :: "r"(saddr), "l"(gaddr));
}
__device__ __forceinline__ void ldsm_x4(uint32_t* r, uint32_t addr) {
    asm volatile("ldmatrix.sync.aligned.m8n8.x4.shared.b16 {%0,%1,%2,%3}, [%4];"
                 : "=r"(r[0]), "=r"(r[1]), "=r"(r[2]), "=r"(r[3]) : "r"(addr));
}
__device__ __forceinline__ void mma16816(float* d, const uint32_t* a, const uint32_t* b) {
    asm volatile(
        "mma.sync.aligned.m16n8k16.row.col.f32.f16.f16.f32 "
        "{%0,%1,%2,%3}, {%4,%5,%6,%7}, {%8,%9}, {%0,%1,%2,%3};"
        : "+f"(d[0]), "+f"(d[1]), "+f"(d[2]), "+f"(d[3])
        : "r"(a[0]), "r"(a[1]), "r"(a[2]), "r"(a[3]), "r"(b[0]), "r"(b[1]));
}
__device__ __forceinline__ uint2 pack_half4(float4 f) {
    __half2 h0 = __floats2half2_rn(f.x, f.y);
    __half2 h1 = __floats2half2_rn(f.z, f.w);
    uint2 u;
    u.x = *reinterpret_cast<uint32_t*>(&h0);
    u.y = *reinterpret_cast<uint32_t*>(&h1);
    return u;
}

// exp with cheap polynomial for tiny args (off-diagonal entries ~1e-4)
__device__ __forceinline__ float exp_mixed(float x) {
    if (fabsf(x) < 0.125f) {
        float p = fmaf(x, 1.0f / 24.0f, 1.0f / 6.0f);
        p = fmaf(p, x, 0.5f);
        p = fmaf(p, x, 1.0f);
        p = fmaf(p, x, 1.0f);
        return p;
    }
    return __expf(x);
}

__device__ __forceinline__ void xconv_range(const float4* __restrict__ x,
                                            uint2* __restrict__ xh,
                                            int start, int end, int stride) {
    #pragma unroll 4
    for (int i = start; i < end; i += stride) {
        float4 f = x[i];
        xh[i] = pack_half4(f);
    }
}

// grid barrier over the SK_CTA sinkhorn CTAs that converts x chunks while
// waiting. All threads advance `cur` in lockstep (same iteration count,
// enforced by the per-loop __syncthreads); every element in [cur0,cend)
// is converted exactly once across waits + final drain.
__device__ __forceinline__ void sk_barrier_work(
    const float4* __restrict__ x, uint2* __restrict__ xh, int& cur, int cend)
{
    __shared__ int s_rel;
    __shared__ int s_gen;
    const int tid = threadIdx.x;
    __syncthreads();
    if (tid == 0) {
        int gen = g_bar_gen;
        s_gen = gen;
        __threadfence();                        // drain my writes
        if (atomicAdd(&g_bar_cnt, 1) == SK_CTA - 1) {
            atomicExch(&g_bar_cnt, 0);
            __threadfence();
            g_bar_gen = gen + 1;
            s_rel = 1;
        } else {
            s_rel = 0;
        }
    }
    __syncthreads();
    while (!s_rel) {
        // one 32 KB micro-chunk of conversion (or idle nap if exhausted)
        if (cur < cend) {
            #pragma unroll
            for (int k = 0; k < 4; k++) {
                int i = cur + tid + k * THR;
                if (i < cend) xh[i] = pack_half4(x[i]);
            }
            cur += 4 * THR;
        } else if (tid == 0) {
            __nanosleep(128);
        }
        if (tid == 0 && g_bar_gen != s_gen) s_rel = 1;
        __syncthreads();                        // publish s_rel / re-loop
    }
    if (tid == 0) __threadfence();              // acquire: invalidate L1
    __syncthreads();
}

// ---------------- kernel 1: fused pre-pass -----------------------------
// CTAs [0, SK_CTA): linear-domain sinkhorn on E = exp(W/T):
//     u' = sqrt(u / (E v)),  v' = sqrt(v / (E^T u)),  10 iters,
//     then wh = E * u ⊗ v (fp16). Their 25% share of xconv is done inside
//     barrier waits (+ drain).
// CTAs [SK_CTA, TOT_CTA): convert first 75% of x fp32 -> fp16.
__global__ void __launch_bounds__(THR, 1) fused_pre_kernel(
    const float4* __restrict__ x, const float* __restrict__ w,
    __half* __restrict__ wh, uint2* __restrict__ xh)
{
    const int tid = threadIdx.x;

    if (blockIdx.x >= SK_CTA) {
        xconv_range(x, xh, (blockIdx.x - SK_CTA) * THR + tid, XSPLIT, XC_CTA * THR);
        return;
    }

    // ---------------- sinkhorn part ----------------
    __shared__ __align__(16) float sE[8 * 1032];   // transpose staging (33 KB)
    __shared__ __align__(16) float su[NSZ];
    __shared__ __align__(16) float sv[NSZ];

    const int b   = blockIdx.x;
    const int wid = tid >> 5, lid = tid & 31;
    const int rb  = b * RPC;                      // own rows / own cols

    int cur  = XSPLIT + b * SKQ;                  // my xconv slice
    const int cend = cur + SKQ;

    // ---- phase 0: E = exp(w*8), ET = E^T, u = v = 1 ----
    #pragma unroll 1
    for (int g = 0; g < RPC / 8; g++) {
        const int r0 = rb + 8 * g;
        const float4* wp = reinterpret_cast<const float4*>(w + (size_t)r0 * NSZ);
        float4* ep = reinterpret_cast<float4*>(g_E + (size_t)r0 * NSZ);
        for (int i = tid; i < 8 * NSZ / 4; i += THR) {
            float4 f = wp[i];
            float4 e;
            e.x = exp_mixed(f.x * 8.0f);
            e.y = exp_mixed(f.y * 8.0f);
            e.z = exp_mixed(f.z * 8.0f);
            e.w = exp_mixed(f.w * 8.0f);
            ep[i] = e;
            int row = i >> 8, c4 = i & 255;
            reinterpret_cast<float4*>(sE + row * 1032)[c4] = e;
        }
        __syncthreads();
        for (int j = tid; j < NSZ; j += THR) {
            float4 a = make_float4(sE[0 * 1032 + j], sE[1 * 1032 + j],
                                   sE[2 * 1032 + j], sE[3 * 1032 + j]);
            float4 c = make_float4(sE[4 * 1032 + j], sE[5 * 1032 + j],
                                   sE[6 * 1032 + j], sE[7 * 1032 + j]);
            float4* tp = reinterpret_cast<float4*>(g_ET + (size_t)j * NSZ + r0);
            tp[0] = a; tp[1] = c;
        }
        __syncthreads();
    }
    if (tid < RPC) {
        g_u[rb + tid] = 1.0f;
        g_v[rb + tid] = 1.0f;
    }
    sk_barrier_work(x, xh, cur, cend);

    // ---- iterations: one barrier each; 1 row + 1 col per warp, interleaved ----
    for (int it = 0; it < N_ITER; it++) {
        for (int i = tid; i < NSZ; i += THR) { su[i] = g_u[i]; sv[i] = g_v[i]; }
        __syncthreads();

        const int idx = rb + wid;   // own row (in E) == own col (row in ET)
        const float4* er = reinterpret_cast<const float4*>(g_E  + (size_t)idx * NSZ);
        const float4* tr = reinterpret_cast<const float4*>(g_ET + (size_t)idx * NSZ);
        const float4* vr = reinterpret_cast<const float4*>(sv);
        const float4* ur = reinterpret_cast<const float4*>(su);
        float s_u = 0.f, s_v = 0.f;
        #pragma unroll
        for (int k = 0; k < 8; k++) {
            float4 e  = er[lid + 32 * k];
            float4 t  = tr[lid + 32 * k];
            float4 v4 = vr[lid + 32 * k];
            float4 u4 = ur[lid + 32 * k];
            s_u = fmaf(e.x, v4.x, s_u); s_u = fmaf(e.y, v4.y, s_u);
            s_u = fmaf(e.z, v4.z, s_u); s_u = fmaf(e.w, v4.w, s_u);
            s_v = fmaf(t.x, u4.x, s_v); s_v = fmaf(t.y, u4.y, s_v);
            s_v = fmaf(t.z, u4.z, s_v); s_v = fmaf(t.w, u4.w, s_v);
        }
        #pragma unroll
        for (int off = 16; off > 0; off >>= 1) {
            s_u += __shfl_xor_sync(0xffffffffu, s_u, off);
            s_v += __shfl_xor_sync(0xffffffffu, s_v, off);
        }
        if (lid == 0) {
            g_u[idx] = sqrtf(su[idx] / s_u);
            g_v[idx] = sqrtf(sv[idx] / s_v);
        }
        sk_barrier_work(x, xh, cur, cend);
    }

    // ---- final: wh[i][j] = E[i][j] * u_i * v_j (fp16), 1 row per warp ----
    for (int i = tid; i < NSZ; i += THR) sv[i] = g_v[i];
    __syncthreads();
    {
        int row = rb + wid;
        float ui = g_u[row];
        const float4* er = reinterpret_cast<const float4*>(g_E + (size_t)row * NSZ);
        const float4* vr = reinterpret_cast<const float4*>(sv);
        uint2* wr = reinterpret_cast<uint2*>(wh + (size_t)row * NSZ);
        #pragma unroll
        for (int k = 0; k < 8; k++) {
            int idx = lid + 32 * k;
            float4 e = er[idx];
            float4 v4 = vr[idx];
            float4 p = make_float4(e.x * ui * v4.x, e.y * ui * v4.y,
                                   e.z * ui * v4.z, e.w * ui * v4.w);
            wr[idx] = pack_half4(p);
        }
    }

    // ---- drain any leftover of my xconv slice ----
    for (; cur < cend; cur += 4 * THR) {
        #pragma unroll
        for (int k = 0; k < 4; k++) {
            int i = cur + tid + k * THR;
            if (i < cend) xh[i] = pack_half4(x[i]);
        }
    }
}

// ---------------- kernel 2: HMMA fp16 GEMM  y = x @ W^T ----------------
// A = g_xh [M, K] K-contig, B = g_wh [N, K] K-contig, out fp32 [M, N].
// 128 threads, 4 warps (2x2), warp tile 64x64.
__device__ __forceinline__ void load_stage(uint32_t sbase, const __half* __restrict__ A,
                                           const __half* __restrict__ B,
                                           int m_base, int n_base, int kc, int tid) {
    const uint32_t sA = sbase, sB = sbase + A_BYTES;
    const __half* ga = A + (size_t)m_base * NSZ + kc * BK;
    const __half* gb = B + (size_t)n_base * NSZ + kc * BK;
    #pragma unroll
    for (int i = 0; i < 8; i++) {
        int id = tid + i * GTHR;
        int row = id >> 3, c = id & 7;
        cp_async16(sA + swz(row * ROWB + c * 16), ga + row * NSZ + c * 8);
    }
    #pragma unroll
    for (int i = 0; i < 8; i++) {
        int id = tid + i * GTHR;
        int row = id >> 3, c = id & 7;
        cp_async16(sB + swz(row * ROWB + c * 16), gb + row * NSZ + c * 8);
    }
}

__global__ void __launch_bounds__(GTHR, 2) gemm_kernel(
    const __half* __restrict__ A, const __half* __restrict__ B,
    float* __restrict__ out)
{
    extern __shared__ __align__(1024) char smem[];
    const uint32_t sb = smem_u32(smem);
    const int tid = threadIdx.x;
    const int lane = tid & 31;
    const int w = tid >> 5;
    const int wm = w >> 1;          // 0..1 -> M offset wm*64
    const int wn = w & 1;           // 0..1 -> N offset wn*64
    const int n_base = blockIdx.x * BN;
    const int m_base = blockIdx.y * BM;

    float acc[4][8][4];
    #pragma unroll
    for (int i = 0; i < 4; i++)
        #pragma unroll
        for (int j = 0; j < 8; j++)
            #pragma unroll
            for (int q = 0; q < 4; q++) acc[i][j][q] = 0.f;

    const uint32_t aRow = (uint32_t)(wm * 64 + (lane & 15)) * ROWB + ((lane >> 4) * 16);
    const uint32_t bRow = (uint32_t)(wn * 64 + ((lane >> 4) * 8) + (lane & 7)) * ROWB
                        + (((lane >> 3) & 1) * 16);

    load_stage(sb + 0 * STAGE_B, A, B, m_base, n_base, 0, tid);
    asm volatile("cp.async.commit_group;" ::: "memory");
    load_stage(sb + 1 * STAGE_B, A, B, m_base, n_base, 1, tid);
    asm volatile("cp.async.commit_group;" ::: "memory");

    int buf = 0;
    #pragma unroll 1
    for (int kc = 0; kc < NKC; kc++) {
        asm volatile("cp.async.wait_group 1;" ::: "memory");
        __syncthreads();

        if (kc + 2 < NKC) {
            int nb = buf + 2; if (nb >= STG) nb -= STG;
            load_stage(sb + nb * STAGE_B, A, B, m_base, n_base, kc + 2, tid);
        }
        asm volatile("cp.async.commit_group;" ::: "memory");

        const uint32_t sA = sb + buf * STAGE_B;
        const uint32_t sB = sA + A_BYTES;
        #pragma unroll
        for (int ks = 0; ks < 4; ks++) {
            uint32_t af[4][4], bf[4][4];
            #pragma unroll
            for (int mt = 0; mt < 4; mt++)
                ldsm_x4(af[mt], sA + swz(aRow + (uint32_t)mt * 16 * ROWB + ks * 32));
            #pragma unroll
            for (int p = 0; p < 4; p++)
                ldsm_x4(bf[p], sB + swz(bRow + (uint32_t)p * 16 * ROWB + ks * 32));
            #pragma unroll
            for (int mt = 0; mt < 4; mt++)
                #pragma unroll
                for (int nt = 0; nt < 8; nt++)
                    mma16816(acc[mt][nt], af[mt], &bf[nt >> 1][(nt & 1) * 2]);
        }
        buf++; if (buf >= STG) buf = 0;
    }

    const int r0 = m_base + wm * 64 + (lane >> 2);
    const int c0 = n_base + wn * 64 + (lane & 3) * 2;
    #pragma unroll
    for (int mt = 0; mt < 4; mt++) {
        #pragma unroll
        for (int nt = 0; nt < 8; nt++) {
            float* p0 = out + (size_t)(r0 + mt * 16) * NSZ + c0 + nt * 8;
            float* p1 = out + (size_t)(r0 + mt * 16 + 8) * NSZ + c0 + nt * 8;
            *reinterpret_cast<float2*>(p0) = make_float2(acc[mt][nt][0], acc[mt][nt][1]);
            *reinterpret_cast<float2*>(p1) = make_float2(acc[mt][nt][2], acc[mt][nt][3]);
        }
    }
}

// ---------------- host ----------------
extern "C" void kernel_launch(void* const* d_in, const int* in_sizes, int n_in,
                              void* d_out, int out_size) {
    const float* x = (const float*)d_in[0];
    const float* w = (const float*)d_in[1];
    if (in_sizes[0] == NSZ * NSZ && in_sizes[1] != NSZ * NSZ) {  // defensive ordering
        x = (const float*)d_in[1];
        w = (const float*)d_in[0];
    }
    float* out = (float*)d_out;

    void* xh_ptr = nullptr;
    void* wh_ptr = nullptr;
    cudaGetSymbolAddress(&xh_ptr, g_xh);
    cudaGetSymbolAddress(&wh_ptr, g_wh);

    cudaFuncSetAttribute(gemm_kernel, cudaFuncAttributeMaxDynamicSharedMemorySize, SMEM_TOTAL);

    // 1) fused: sinkhorn (CTAs 0..63, + xconv during barrier waits)
    //           + dedicated xconv (CTAs 64..147)
    fused_pre_kernel<<<TOT_CTA, THR>>>((const float4*)x, w,
                                       (__half*)wh_ptr, (uint2*)xh_ptr);

    // 2) GEMM
    gemm_kernel<<<dim3(NSZ / BN, M_TOTAL / BM, 1), GTHR, SMEM_TOTAL>>>(
        (const __half*)xh_ptr, (const __half*)wh_ptr, out);
}

// round 11
// speedup vs baseline: 1.1437x; 1.0862x over previous
#include <cuda_runtime.h>
#include <cuda_fp16.h>
#include <cstdint>

// ---------------- problem constants ----------------
#define NSZ      1024
#define M_TOTAL  32768

// GEMM tiling: CTA 128x128, 4 warps of 64x64
#define BM 128
#define BN 128
#define BK 64                       // halves per K chunk (128 bytes per smem row)
#define STG 3
#define NKC (NSZ / BK)              // 16 K-chunks
#define ROWB 128                    // bytes per smem row
#define A_BYTES (BM * ROWB)         // 16384
#define B_BYTES (BN * ROWB)         // 16384
#define STAGE_B (A_BYTES + B_BYTES) // 32768
#define SMEM_TOTAL (STG * STAGE_B)  // 98304
#define GTHR 128

// fused pre-pass: 64 sinkhorn CTAs + 84 xconv CTAs, all co-resident
#define SK_CTA  64
#define TOT_CTA 148
#define THR     512
#define RPC     (NSZ / SK_CTA)      // 16 rows (and cols) per sinkhorn CTA
#define N_ITER  10
#define TOTAL4  (M_TOTAL * NSZ / 4) // 8388608 float4s of x
#define CHUNK4  (8 * THR)           // 4096 float4s = 64 KB per steal chunk
#define NCHK    (TOTAL4 / CHUNK4)   // 2048 chunks

// ---------------- scratch (no allocation allowed) ----------------
__device__ __align__(1024) __half g_xh[(size_t)M_TOTAL * NSZ];   // 64 MiB fp16 x
__device__ __align__(1024) __half g_wh[NSZ * NSZ];               // 2 MiB fp16 W
__device__ __align__(1024) float  g_E [NSZ * NSZ];               // 4 MiB exp(W/T)
__device__ __align__(1024) float  g_ET[NSZ * NSZ];               // 4 MiB transpose
__device__ float g_u[NSZ];
__device__ float g_v[NSZ];
__device__ int          g_bar_cnt;
__device__ volatile int g_bar_gen;
__device__ int          g_xc_cnt;   // xconv chunk queue (reset by gemm_kernel)

// ---------------- helpers ----------------
__device__ __forceinline__ uint32_t smem_u32(const void* p) {
    uint32_t a;
    asm("{ .reg .u64 t; cvta.to.shared.u64 t, %1; cvt.u32.u64 %0, t; }" : "=r"(a) : "l"(p));
    return a;
}
__device__ __forceinline__ uint32_t swz(uint32_t o) {       // 128B swizzle
    return o ^ ((o >> 3) & 0x70);
}
__device__ __forceinline__ void cp_async16(uint32_t saddr, const void* gaddr) {
    asm volatile("cp.async.cg.shared.global [%0], [%1], 16;" :: "r"(saddr), "l"(gaddr));
}
__device__ __forceinline__ void ldsm_x4(uint32_t* r, uint32_t addr) {
    asm volatile("ldmatrix.sync.aligned.m8n8.x4.shared.b16 {%0,%1,%2,%3}, [%4];"
                 : "=r"(r[0]), "=r"(r[1]), "=r"(r[2]), "=r"(r[3]) : "r"(addr));
}
__device__ __forceinline__ void mma16816(float* d, const uint32_t* a, const uint32_t* b) {
    asm volatile(
        "mma.sync.aligned.m16n8k16.row.col.f32.f16.f16.f32 "
        "{%0,%1,%2,%3}, {%4,%5,%6,%7}, {%8,%9}, {%0,%1,%2,%3};"
        : "+f"(d[0]), "+f"(d[1]), "+f"(d[2]), "+f"(d[3])
        : "r"(a[0]), "r"(a[1]), "r"(a[2]), "r"(a[3]), "r"(b[0]), "r"(b[1]));
}
__device__ __forceinline__ uint2 pack_half4(float4 f) {
    __half2 h0 = __floats2half2_rn(f.x, f.y);
    __half2 h1 = __floats2half2_rn(f.z, f.w);
    uint2 u;
    u.x = *reinterpret_cast<uint32_t*>(&h0);
    u.y = *reinterpret_cast<uint32_t*>(&h1);
    return u;
}

// grid-wide barrier over the SK_CTA sinkhorn CTAs (R7-proven form).
__device__ __forceinline__ void sk_barrier() {
    __syncthreads();
    if (threadIdx.x == 0) {
        int gen = g_bar_gen;
        __threadfence();
        if (atomicAdd(&g_bar_cnt, 1) == SK_CTA - 1) {
            atomicExch(&g_bar_cnt, 0);
            __threadfence();
            g_bar_gen = gen + 1;
        } else {
            while (g_bar_gen == gen) { __nanosleep(64); }
        }
        __threadfence();
    }
    __syncthreads();
}

// exp with cheap polynomial for tiny args (off-diagonal entries ~1e-4)
__device__ __forceinline__ float exp_mixed(float x) {
    if (fabsf(x) < 0.125f) {
        float p = fmaf(x, 1.0f / 24.0f, 1.0f / 6.0f);
        p = fmaf(p, x, 0.5f);
        p = fmaf(p, x, 1.0f);
        p = fmaf(p, x, 1.0f);
        return p;
    }
    return __expf(x);
}

// work-stealing xconv: pull 64 KB chunks off the global queue until empty.
// 8 independent LDG.128 in flight per thread (MLP=8).
__device__ __forceinline__ void xconv_steal(const float4* __restrict__ x,
                                            uint2* __restrict__ xh) {
    __shared__ int s_chunk;
    const int tid = threadIdx.x;
    for (;;) {
        if (tid == 0) s_chunk = atomicAdd(&g_xc_cnt, 1);
        __syncthreads();
        const int c = s_chunk;
        __syncthreads();
        if (c >= NCHK) break;
        const int base = c * CHUNK4 + tid;
        float4 f[8];
        #pragma unroll
        for (int k = 0; k < 8; k++) f[k] = x[base + k * THR];
        #pragma unroll
        for (int k = 0; k < 8; k++) xh[base + k * THR] = pack_half4(f[k]);
    }
}

// ---------------- kernel 1: fused pre-pass -----------------------------
// CTAs [0, SK_CTA): linear-domain sinkhorn on E = exp(W/T):
//     u' = sqrt(u / (E v)),  v' = sqrt(v / (E^T u)),  10 iters,
//     then wh = E * u ⊗ v (fp16), then join the xconv queue.
// CTAs [SK_CTA, TOT_CTA): pull xconv chunks from t=0.
__global__ void __launch_bounds__(THR, 1) fused_pre_kernel(
    const float4* __restrict__ x, const float* __restrict__ w,
    __half* __restrict__ wh, uint2* __restrict__ xh)
{
    const int tid = threadIdx.x;

    if (blockIdx.x >= SK_CTA) {
        xconv_steal(x, xh);
        return;
    }

    // ---------------- sinkhorn part ----------------
    __shared__ __align__(16) float sE[8 * 1032];   // transpose staging (33 KB)
    __shared__ __align__(16) float su[NSZ];
    __shared__ __align__(16) float sv[NSZ];

    const int b   = blockIdx.x;
    const int wid = tid >> 5, lid = tid & 31;
    const int rb  = b * RPC;                      // own rows / own cols

    // ---- phase 0: E = exp(w*8), ET = E^T, u = v = 1 ----
    #pragma unroll 1
    for (int g = 0; g < RPC / 8; g++) {
        const int r0 = rb + 8 * g;
        const float4* wp = reinterpret_cast<const float4*>(w + (size_t)r0 * NSZ);
        float4* ep = reinterpret_cast<float4*>(g_E + (size_t)r0 * NSZ);
        for (int i = tid; i < 8 * NSZ / 4; i += THR) {
            float4 f = wp[i];
            float4 e;
            e.x = exp_mixed(f.x * 8.0f);
            e.y = exp_mixed(f.y * 8.0f);
            e.z = exp_mixed(f.z * 8.0f);
            e.w = exp_mixed(f.w * 8.0f);
            ep[i] = e;
            int row = i >> 8, c4 = i & 255;
            reinterpret_cast<float4*>(sE + row * 1032)[c4] = e;
        }
        __syncthreads();
        for (int j = tid; j < NSZ; j += THR) {
            float4 a = make_float4(sE[0 * 1032 + j], sE[1 * 1032 + j],
                                   sE[2 * 1032 + j], sE[3 * 1032 + j]);
            float4 c = make_float4(sE[4 * 1032 + j], sE[5 * 1032 + j],
                                   sE[6 * 1032 + j], sE[7 * 1032 + j]);
            float4* tp = reinterpret_cast<float4*>(g_ET + (size_t)j * NSZ + r0);
            tp[0] = a; tp[1] = c;
        }
        __syncthreads();
    }
    if (tid < RPC) {
        g_u[rb + tid] = 1.0f;
        g_v[rb + tid] = 1.0f;
    }
    sk_barrier();

    // ---- iterations: one barrier each; 1 row + 1 col per warp, interleaved ----
    for (int it = 0; it < N_ITER; it++) {
        for (int i = tid; i < NSZ; i += THR) { su[i] = g_u[i]; sv[i] = g_v[i]; }
        __syncthreads();

        const int idx = rb + wid;   // own row (in E) == own col (row in ET)
        const float4* er = reinterpret_cast<const float4*>(g_E  + (size_t)idx * NSZ);
        const float4* tr = reinterpret_cast<const float4*>(g_ET + (size_t)idx * NSZ);
        const float4* vr = reinterpret_cast<const float4*>(sv);
        const float4* ur = reinterpret_cast<const float4*>(su);
        float s_u = 0.f, s_v = 0.f;
        #pragma unroll
        for (int k = 0; k < 8; k++) {
            float4 e  = er[lid + 32 * k];
            float4 t  = tr[lid + 32 * k];
            float4 v4 = vr[lid + 32 * k];
            float4 u4 = ur[lid + 32 * k];
            s_u = fmaf(e.x, v4.x, s_u); s_u = fmaf(e.y, v4.y, s_u);
            s_u = fmaf(e.z, v4.z, s_u); s_u = fmaf(e.w, v4.w, s_u);
            s_v = fmaf(t.x, u4.x, s_v); s_v = fmaf(t.y, u4.y, s_v);
            s_v = fmaf(t.z, u4.z, s_v); s_v = fmaf(t.w, u4.w, s_v);
        }
        #pragma unroll
        for (int off = 16; off > 0; off >>= 1) {
            s_u += __shfl_xor_sync(0xffffffffu, s_u, off);
            s_v += __shfl_xor_sync(0xffffffffu, s_v, off);
        }
        if (lid == 0) {
            g_u[idx] = sqrtf(su[idx] / s_u);
            g_v[idx] = sqrtf(sv[idx] / s_v);
        }
        sk_barrier();
    }

    // ---- final: wh[i][j] = E[i][j] * u_i * v_j (fp16), 1 row per warp ----
    for (int i = tid; i < NSZ; i += THR) sv[i] = g_v[i];
    __syncthreads();
    {
        int row = rb + wid;
        float ui = g_u[row];
        const float4* er = reinterpret_cast<const float4*>(g_E + (size_t)row * NSZ);
        const float4* vr = reinterpret_cast<const float4*>(sv);
        uint2* wr = reinterpret_cast<uint2*>(wh + (size_t)row * NSZ);
        #pragma unroll
        for (int k = 0; k < 8; k++) {
            int idx = lid + 32 * k;
            float4 e = er[idx];
            float4 v4 = vr[idx];
            float4 p = make_float4(e.x * ui * v4.x, e.y * ui * v4.y,
                                   e.z * ui * v4.z, e.w * ui * v4.w);
            wr[idx] = pack_half4(p);
        }
    }

    // ---- join the xconv queue ----
    xconv_steal(x, xh);
}

// ---------------- kernel 2: HMMA fp16 GEMM  y = x @ W^T ----------------
// A = g_xh [M, K] K-contig, B = g_wh [N, K] K-contig, out fp32 [M, N].
// 128 threads, 4 warps (2x2), warp tile 64x64.
__device__ __forceinline__ void load_stage(uint32_t sbase, const __half* __restrict__ A,
                                           const __half* __restrict__ B,
                                           int m_base, int n_base, int kc, int tid) {
    const uint32_t sA = sbase, sB = sbase + A_BYTES;
    const __half* ga = A + (size_t)m_base * NSZ + kc * BK;
    const __half* gb = B + (size_t)n_base * NSZ + kc * BK;
    #pragma unroll
    for (int i = 0; i < 8; i++) {
        int id = tid + i * GTHR;
        int row = id >> 3, c = id & 7;
        cp_async16(sA + swz(row * ROWB + c * 16), ga + row * NSZ + c * 8);
    }
    #pragma unroll
    for (int i = 0; i < 8; i++) {
        int id = tid + i * GTHR;
        int row = id >> 3, c = id & 7;
        cp_async16(sB + swz(row * ROWB + c * 16), gb + row * NSZ + c * 8);
    }
}

__global__ void __launch_bounds__(GTHR, 2) gemm_kernel(
    const __half* __restrict__ A, const __half* __restrict__ B,
    float* __restrict__ out)
{
    // reset the xconv steal queue for the next graph replay (pre-pass of the
    // next launch is strictly ordered after this kernel).
    if (blockIdx.x == 0 && blockIdx.y == 0 && threadIdx.x == 0)
        g_xc_cnt = 0;

    extern __shared__ __align__(1024) char smem[];
    const uint32_t sb = smem_u32(smem);
    const int tid = threadIdx.x;
    const int lane = tid & 31;
    const int w = tid >> 5;
    const int wm = w >> 1;          // 0..1 -> M offset wm*64
    const int wn = w & 1;           // 0..1 -> N offset wn*64
    const int n_base = blockIdx.x * BN;
    const int m_base = blockIdx.y * BM;

    float acc[4][8][4];
    #pragma unroll
    for (int i = 0; i < 4; i++)
        #pragma unroll
        for (int j = 0; j < 8; j++)
            #pragma unroll
            for (int q = 0; q < 4; q++) acc[i][j][q] = 0.f;

    const uint32_t aRow = (uint32_t)(wm * 64 + (lane & 15)) * ROWB + ((lane >> 4) * 16);
    const uint32_t bRow = (uint32_t)(wn * 64 + ((lane >> 4) * 8) + (lane & 7)) * ROWB
                        + (((lane >> 3) & 1) * 16);

    load_stage(sb + 0 * STAGE_B, A, B, m_base, n_base, 0, tid);
    asm volatile("cp.async.commit_group;" ::: "memory");
    load_stage(sb + 1 * STAGE_B, A, B, m_base, n_base, 1, tid);
    asm volatile("cp.async.commit_group;" ::: "memory");

    int buf = 0;
    #pragma unroll 1
    for (int kc = 0; kc < NKC; kc++) {
        asm volatile("cp.async.wait_group 1;" ::: "memory");
        __syncthreads();

        if (kc + 2 < NKC) {
            int nb = buf + 2; if (nb >= STG) nb -= STG;
            load_stage(sb + nb * STAGE_B, A, B, m_base, n_base, kc + 2, tid);
        }
        asm volatile("cp.async.commit_group;" ::: "memory");

        const uint32_t sA = sb + buf * STAGE_B;
        const uint32_t sB = sA + A_BYTES;
        #pragma unroll
        for (int ks = 0; ks < 4; ks++) {
            uint32_t af[4][4], bf[4][4];
            #pragma unroll
            for (int mt = 0; mt < 4; mt++)
                ldsm_x4(af[mt], sA + swz(aRow + (uint32_t)mt * 16 * ROWB + ks * 32));
            #pragma unroll
            for (int p = 0; p < 4; p++)
                ldsm_x4(bf[p], sB + swz(bRow + (uint32_t)p * 16 * ROWB + ks * 32));
            #pragma unroll
            for (int mt = 0; mt < 4; mt++)
                #pragma unroll
                for (int nt = 0; nt < 8; nt++)
                    mma16816(acc[mt][nt], af[mt], &bf[nt >> 1][(nt & 1) * 2]);
        }
        buf++; if (buf >= STG) buf = 0;
    }

    const int r0 = m_base + wm * 64 + (lane >> 2);
    const int c0 = n_base + wn * 64 + (lane & 3) * 2;
    #pragma unroll
    for (int mt = 0; mt < 4; mt++) {
        #pragma unroll
        for (int nt = 0; nt < 8; nt++) {
            float* p0 = out + (size_t)(r0 + mt * 16) * NSZ + c0 + nt * 8;
            float* p1 = out + (size_t)(r0 + mt * 16 + 8) * NSZ + c0 + nt * 8;
            *reinterpret_cast<float2*>(p0) = make_float2(acc[mt][nt][0], acc[mt][nt][1]);
            *reinterpret_cast<float2*>(p1) = make_float2(acc[mt][nt][2], acc[mt][nt][3]);
        }
    }
}

// ---------------- host ----------------
extern "C" void kernel_launch(void* const* d_in, const int* in_sizes, int n_in,
                              void* d_out, int out_size) {
    const float* x = (const float*)d_in[0];
    const float* w = (const float*)d_in[1];
    if (in_sizes[0] == NSZ * NSZ && in_sizes[1] != NSZ * NSZ) {  // defensive ordering
        x = (const float*)d_in[1];
        w = (const float*)d_in[0];
    }
    float* out = (float*)d_out;

    void* xh_ptr = nullptr;
    void* wh_ptr = nullptr;
    cudaGetSymbolAddress(&xh_ptr, g_xh);
    cudaGetSymbolAddress(&wh_ptr, g_wh);

    cudaFuncSetAttribute(gemm_kernel, cudaFuncAttributeMaxDynamicSharedMemorySize, SMEM_TOTAL);

    // 1) fused: sinkhorn (CTAs 0..63) + work-stealing xconv (all CTAs)
    fused_pre_kernel<<<TOT_CTA, THR>>>((const float4*)x, w,
                                       (__half*)wh_ptr, (uint2*)xh_ptr);

    // 2) GEMM (also resets the steal queue for the next replay)
    gemm_kernel<<<dim3(NSZ / BN, M_TOTAL / BM, 1), GTHR, SMEM_TOTAL>>>(
        (const __half*)xh_ptr, (const __half*)wh_ptr, out);
}